// round 14
// baseline (speedup 1.0000x reference)
#include <cuda_runtime.h>
#include <cuda_bf16.h>
#include <math.h>

#define T_LEN 100000
#define WIN   336
#define OUTSZ 48
#define SEAS  168
#define N_ROWS (T_LEN - WIN - OUTSZ + 1)   // 99617
#define M_PAD  99712                        // 779 * 128
#define STD_NOISE 0.001f
#define LVP_F 50.0f
#define CHUNK 160
#define LPL 5
#define GROWS 24                            // rows per worker group

#define G1_STAGE 62976
#define G1_SMEM  (2 * G1_STAGE)
#define G2_STAGE 50688
#define G2_SMEM  (2 * G2_STAGE)

// ---------------- device scratch ----------------
__device__ float g_levels[T_LEN];
__device__ float g_llev[T_LEN];
__device__ float g_c[T_LEN];
__device__ unsigned g_progress;
__device__ __nv_bfloat16 g_a_hi[(size_t)M_PAD * WIN];
__device__ __nv_bfloat16 g_a_lo[(size_t)M_PAD * WIN];
__device__ __nv_bfloat16 g_h_hi[(size_t)M_PAD * WIN];
__device__ __nv_bfloat16 g_h_lo[(size_t)M_PAD * WIN];
__device__ __nv_bfloat16 g_w1h[WIN * WIN], g_w1l[WIN * WIN];
__device__ __nv_bfloat16 g_w2h[WIN * OUTSZ], g_w2l[WIN * OUTSZ];

// ---------------- compile-time threefry ----------------
struct TF2 { unsigned y0, y1; };
__host__ __device__ constexpr unsigned tf_rotl(unsigned x, int r) {
    return (x << r) | (x >> (32 - r));
}
__host__ __device__ constexpr TF2 tf2x32_const(unsigned k0, unsigned k1,
                                               unsigned x0, unsigned x1) {
    unsigned ks2 = 0x1BD11BDAu ^ k0 ^ k1;
    const int R[8] = {13, 15, 26, 6, 17, 29, 16, 24};
    x0 += k0; x1 += k1;
    for (int i = 0; i < 4; i++) { x0 += x1; x1 = tf_rotl(x1, R[i]); x1 ^= x0; }
    x0 += k1;  x1 += ks2 + 1u;
    for (int i = 4; i < 8; i++) { x0 += x1; x1 = tf_rotl(x1, R[i]); x1 ^= x0; }
    x0 += ks2; x1 += k0 + 2u;
    for (int i = 0; i < 4; i++) { x0 += x1; x1 = tf_rotl(x1, R[i]); x1 ^= x0; }
    x0 += k0;  x1 += k1 + 3u;
    for (int i = 4; i < 8; i++) { x0 += x1; x1 = tf_rotl(x1, R[i]); x1 ^= x0; }
    x0 += k1;  x1 += ks2 + 4u;
    for (int i = 0; i < 4; i++) { x0 += x1; x1 = tf_rotl(x1, R[i]); x1 ^= x0; }
    x0 += ks2; x1 += k0 + 5u;
    return TF2{x0, x1};
}

// ---------------- runtime threefry2x32 (JAX partitionable) ----------------
__device__ __forceinline__ void threefry2x32(unsigned k0, unsigned k1,
                                             unsigned x0, unsigned x1,
                                             unsigned& y0, unsigned& y1) {
    unsigned ks2 = 0x1BD11BDAu ^ k0 ^ k1;
#define TF_RND(r) { x0 += x1; x1 = (x1 << (r)) | (x1 >> (32 - (r))); x1 ^= x0; }
    x0 += k0; x1 += k1;
    TF_RND(13) TF_RND(15) TF_RND(26) TF_RND(6)
    x0 += k1;  x1 += ks2 + 1u;
    TF_RND(17) TF_RND(29) TF_RND(16) TF_RND(24)
    x0 += ks2; x1 += k0 + 2u;
    TF_RND(13) TF_RND(15) TF_RND(26) TF_RND(6)
    x0 += k0;  x1 += k1 + 3u;
    TF_RND(17) TF_RND(29) TF_RND(16) TF_RND(24)
    x0 += k1;  x1 += ks2 + 4u;
    TF_RND(13) TF_RND(15) TF_RND(26) TF_RND(6)
    x0 += ks2; x1 += k0 + 5u;
#undef TF_RND
    y0 = x0; y1 = x1;
}
__device__ __forceinline__ unsigned tf_bits32(unsigned k0, unsigned k1, unsigned i) {
    unsigned y0, y1;
    threefry2x32(k0, k1, 0u, i, y0, y1);
    return y0 ^ y1;
}

__device__ __forceinline__ float bits_to_normal(unsigned bits) {
    float f = __uint_as_float((bits >> 9) | 0x3f800000u) - 1.0f;
    const float LO = -0.99999994f;
    float u = fmaxf(LO, f * 2.0f + LO);
    float x = u;
    float w = -__logf(fmaf(-x, x, 1.0f));
    float p;
    if (w < 5.0f) {
        w -= 2.5f;
        p =              2.81022636e-08f;
        p = fmaf(p, w,   3.43273939e-07f);
        p = fmaf(p, w,  -3.5233877e-06f);
        p = fmaf(p, w,  -4.39150654e-06f);
        p = fmaf(p, w,   0.00021858087f);
        p = fmaf(p, w,  -0.00125372503f);
        p = fmaf(p, w,  -0.00417768164f);
        p = fmaf(p, w,   0.246640727f);
        p = fmaf(p, w,   1.50140941f);
    } else {
        w = sqrtf(w) - 3.0f;
        p =             -0.000200214257f;
        p = fmaf(p, w,   0.000100950558f);
        p = fmaf(p, w,   0.00134934322f);
        p = fmaf(p, w,  -0.00367342844f);
        p = fmaf(p, w,   0.00573950773f);
        p = fmaf(p, w,  -0.0076224613f);
        p = fmaf(p, w,   0.00943887047f);
        p = fmaf(p, w,   1.00167406f);
        p = fmaf(p, w,   2.83297682f);
    }
    return 1.41421356237f * (p * x);
}

// ---------------- split helper ----------------
__device__ __forceinline__ void split_bf16(float v, __nv_bfloat16& hi, __nv_bfloat16& lo) {
    hi = __float2bfloat16(v);
    lo = __float2bfloat16(v - __bfloat162float(hi));
}

// ---------------- weight splits ----------------
__global__ void wsplit1_kernel(const float* __restrict__ W1) {
    int i = blockIdx.x * blockDim.x + threadIdx.x;
    if (i < WIN * WIN) split_bf16(W1[i], g_w1h[i], g_w1l[i]);
}
__global__ void wsplit2_kernel(const float* __restrict__ W2) {
    int i = blockIdx.x * blockDim.x + threadIdx.x;
    if (i < WIN * OUTSZ) split_bf16(W2[i], g_w2h[i], g_w2l[i]);
}

// ---------------- zero A tail rows + reset progress ----------------
__global__ void zero_tail_kernel() {
    if (blockIdx.x == 0 && threadIdx.x == 0) g_progress = 0u;
    const unsigned start = (unsigned)N_ROWS * WIN;
    const unsigned total = (unsigned)M_PAD * WIN - start;
    unsigned i = 2u * (blockIdx.x * blockDim.x + threadIdx.x);
    if (i < total) {
        *reinterpret_cast<unsigned*>(&g_a_hi[start + i]) = 0u;
        *reinterpret_cast<unsigned*>(&g_a_lo[start + i]) = 0u;
    }
}

// ---------------- FUSED: scan (block 0) + gen inputs/labels (workers) ----------------
__global__ void __launch_bounds__(1024, 1)
fused_scan_gen_kernel(const float* __restrict__ x,
                      const float* __restrict__ lvl_coef,
                      const float* __restrict__ seas_coef,
                      const float* __restrict__ seas_params,
                      float* __restrict__ d_out) {
    if (blockIdx.x == 0) {
        // ---------- producer: warp 0 scan; other warps exit ----------
        if (threadIdx.x >= 32) return;
        __shared__ float ring[512];
        const int lane = threadIdx.x;
        const unsigned FULL = 0xFFFFFFFFu;
        for (int i = lane; i < SEAS; i += 32) ring[i] = expf(seas_params[i]);
        __syncwarp();
        if (lane == 0) ring[SEAS] = ring[0];
        __syncwarp();

        const float a = 1.0f / (1.0f + expf(-lvl_coef[0]));
        const float g = 1.0f / (1.0f + expf(-seas_coef[0]));
        const float b = 1.0f - a;
        const float omg = 1.0f - g;
        const float b5 = b * b * b * b * b;
        const float bl = __powf(b5, (float)lane);

        float level = x[0] / ring[0];
        if (lane == 0) {
            g_levels[0] = level;
            g_llev[0] = __logf(level);
            g_c[0] = __logf(x[0]) - __logf(ring[0]);
        }

        float xn[LPL];
        {
            const int base = 1 + lane * LPL;
#pragma unroll
            for (int j = 0; j < LPL; j++)
                xn[j] = (base + j < T_LEN) ? __ldg(&x[base + j]) : 1.0f;
        }

        int ck = 0;
        for (int t0 = 1; t0 < T_LEN; t0 += CHUNK) {
            const int base = t0 + lane * LPL;
            float xi[LPL];
#pragma unroll
            for (int j = 0; j < LPL; j++) xi[j] = xn[j];
            {
                const int nbase = t0 + CHUNK + lane * LPL;
#pragma unroll
                for (int j = 0; j < LPL; j++)
                    xn[j] = (nbase + j < T_LEN) ? __ldg(&x[nbase + j]) : 1.0f;
            }
            float se[LPL], c[LPL];
#pragma unroll
            for (int j = 0; j < LPL; j++) {
                int t = base + j;
                if (t < T_LEN) {
                    se[j] = ring[t & 511];
                    c[j]  = __fdividef(a * xi[j], se[j]);
                    g_c[t] = __logf(xi[j]) - __logf(se[j]);   // off critical path
                } else { se[j] = 1.0f; c[j] = 0.0f; }
            }
            float s = 0.0f;
#pragma unroll
            for (int j = 0; j < LPL; j++) s = fmaf(b, s, c[j]);
            float S = s;
            float m = b5;
#pragma unroll
            for (int off = 1; off < 32; off <<= 1) {
                float up = __shfl_up_sync(FULL, S, off);
                if (lane >= off) S = fmaf(m, up, S);
                m = m * m;
            }
            float Sprev = __shfl_up_sync(FULL, S, 1);
            if (lane == 0) Sprev = 0.0f;
            float lvl = fmaf(bl, level, Sprev);
#pragma unroll
            for (int j = 0; j < LPL; j++) {
                int t = base + j;
                if (t < T_LEN) {
                    lvl = fmaf(b, lvl, c[j]);
                    g_levels[t] = lvl;
                    g_llev[t] = __logf(lvl);
                    float ns = fmaf(omg, se[j], __fdividef(g * xi[j], lvl));
                    ring[(t + SEAS) & 511] = ns;
                }
            }
            level = __shfl_sync(FULL, lvl, 31);
            ck++;
            if ((ck & 3) == 0) {
                __threadfence();            // all lanes flush their STGs
                __syncwarp();
                if (lane == 0) {
                    unsigned done = (unsigned)min(t0 + CHUNK, T_LEN);
                    atomicExch(&g_progress, done);
                }
                __syncwarp();
            } else {
                __syncwarp();
            }
        }
        __threadfence();
        __syncwarp();
        if (lane == 0) atomicExch(&g_progress, (unsigned)T_LEN);
        return;
    }

    // ---------- consumers: generate inputs (bf16 hi/lo) + labels ----------
    constexpr TF2 K1 = tf2x32_const(0u, 1u, 0u, 0u);
    constexpr TF2 K2 = tf2x32_const(0u, 1u, 0u, 1u);
    const int nworkers = gridDim.x - 1;
    const int wrk = blockIdx.x - 1;
    const unsigned NGROUPS = (N_ROWS + GROWS - 1) / GROWS;
    float* labels = d_out + (size_t)N_ROWS * OUTSZ;

    for (unsigned gidx = wrk; gidx < NGROUPS; gidx += nworkers) {
        const unsigned n0 = gidx * GROWS;
        const unsigned n1 = min(n0 + GROWS, (unsigned)N_ROWS);
        const unsigned rows = n1 - n0;
        const unsigned needed = n1 - 1 + WIN + OUTSZ;   // <= T_LEN
        if (threadIdx.x == 0) {
            while (atomicAdd(&g_progress, 0u) < needed) __nanosleep(200);
        }
        __syncthreads();
        __threadfence();   // acquire: order subsequent data reads after observed publish

        // inputs: rows * 84 float4-groups of 4 bf16 elements
        const unsigned e4in = rows * (WIN / 4);
        for (unsigned i4 = threadIdx.x; i4 < e4in; i4 += 1024) {
            unsigned n = n0 + i4 / (WIN / 4);
            unsigned w = (i4 % (WIN / 4)) * 4;
            float llv = g_llev[n + WIN];
            unsigned ibase = n * WIN + w;
            __nv_bfloat16 hi[4], lo[4];
#pragma unroll
            for (int j = 0; j < 4; j++) {
                float z = bits_to_normal(tf_bits32(K1.y0, K1.y1, ibase + j));
                float v = g_c[n + w + j] - llv + STD_NOISE * z;
                split_bf16(v, hi[j], lo[j]);
            }
            *reinterpret_cast<__nv_bfloat162*>(&g_a_hi[ibase])     = __nv_bfloat162{hi[0], hi[1]};
            *reinterpret_cast<__nv_bfloat162*>(&g_a_hi[ibase + 2]) = __nv_bfloat162{hi[2], hi[3]};
            *reinterpret_cast<__nv_bfloat162*>(&g_a_lo[ibase])     = __nv_bfloat162{lo[0], lo[1]};
            *reinterpret_cast<__nv_bfloat162*>(&g_a_lo[ibase + 2]) = __nv_bfloat162{lo[2], lo[3]};
        }
        // labels: rows * 12 float4-groups
        const unsigned e4lb = rows * (OUTSZ / 4);
        for (unsigned i4 = threadIdx.x; i4 < e4lb; i4 += 1024) {
            unsigned n = n0 + i4 / (OUTSZ / 4);
            unsigned o = (i4 % (OUTSZ / 4)) * 4;
            float llv = g_llev[n + WIN];
            unsigned ibase = n * OUTSZ + o;
            float v[4];
#pragma unroll
            for (int j = 0; j < 4; j++) {
                float z = bits_to_normal(tf_bits32(K2.y0, K2.y1, ibase + j));
                v[j] = g_c[n + WIN + o + j] - llv + STD_NOISE * z;
            }
            *reinterpret_cast<float4*>(&labels[ibase]) = make_float4(v[0], v[1], v[2], v[3]);
        }
    }
}

// ---------------- level variation loss (precise logf from levels) ----------------
__global__ void loss_kernel(float* __restrict__ d_out) {
    __shared__ double sh[1024];
    double acc = 0.0;
    for (int i = threadIdx.x; i < T_LEN - 2; i += 1024) {
        float l0 = logf(g_levels[i]);
        float l1 = logf(g_levels[i + 1]);
        float l2 = logf(g_levels[i + 2]);
        float d2 = (l2 - l1) - (l1 - l0);
        acc += (double)d2 * (double)d2;
    }
    sh[threadIdx.x] = acc;
    __syncthreads();
    for (int s = 512; s > 0; s >>= 1) {
        if (threadIdx.x < s) sh[threadIdx.x] += sh[threadIdx.x + s];
        __syncthreads();
    }
    if (threadIdx.x == 0)
        d_out[2 * (size_t)N_ROWS * OUTSZ] = (float)(sh[0] / (double)(T_LEN - 2) * (double)LVP_F);
}

// ---------------- mma / cp.async helpers ----------------
__device__ __forceinline__ unsigned sm_u32(const void* p) {
    return (unsigned)__cvta_generic_to_shared(p);
}
__device__ __forceinline__ void ldsm_x4(unsigned* d, unsigned addr) {
    asm volatile("ldmatrix.sync.aligned.m8n8.x4.shared.b16 {%0,%1,%2,%3}, [%4];"
                 : "=r"(d[0]), "=r"(d[1]), "=r"(d[2]), "=r"(d[3]) : "r"(addr));
}
__device__ __forceinline__ void ldsm_x4t(unsigned* d, unsigned addr) {
    asm volatile("ldmatrix.sync.aligned.m8n8.x4.trans.shared.b16 {%0,%1,%2,%3}, [%4];"
                 : "=r"(d[0]), "=r"(d[1]), "=r"(d[2]), "=r"(d[3]) : "r"(addr));
}
__device__ __forceinline__ void mma16816(float* c, const unsigned* a, unsigned b0, unsigned b1) {
    asm volatile("mma.sync.aligned.m16n8k16.row.col.f32.bf16.bf16.f32 "
                 "{%0,%1,%2,%3}, {%4,%5,%6,%7}, {%8,%9}, {%0,%1,%2,%3};"
                 : "+f"(c[0]), "+f"(c[1]), "+f"(c[2]), "+f"(c[3])
                 : "r"(a[0]), "r"(a[1]), "r"(a[2]), "r"(a[3]), "r"(b0), "r"(b1));
}
__device__ __forceinline__ void cp16(void* s, const void* g) {
    asm volatile("cp.async.cg.shared.global [%0], [%1], 16;"
                 :: "r"(sm_u32(s)), "l"(g));
}
__device__ __forceinline__ void cp16_pred(void* s, const void* g, bool ok) {
    int sz = ok ? 16 : 0;
    asm volatile("cp.async.cg.shared.global [%0], [%1], 16, %2;"
                 :: "r"(sm_u32(s)), "l"(g), "r"(sz));
}
__device__ __forceinline__ void cp_commit() {
    asm volatile("cp.async.commit_group;");
}
template<int N>
__device__ __forceinline__ void cp_wait() {
    asm volatile("cp.async.wait_group %0;" :: "n"(N));
}

// ---------------- GEMM1: dual-accumulator 3-term bf16, 2-stage cp.async ----------
#define G1_AST 72
#define G1_BST 136
__global__ void __launch_bounds__(256, 1)
gemm1_kernel(const float* __restrict__ bias) {
    extern __shared__ char smem[];
    const int tid = threadIdx.x;
    const int wid = tid >> 5, lane = tid & 31;
    const int wm = wid >> 2, wn = wid & 3;
    const int row0 = blockIdx.x * 128;
    const int col0 = blockIdx.y * 128;
    const int lrow = lane & 15, lcol = (lane >> 4) << 3;

    auto sAh = [&](int s) { return (__nv_bfloat16*)(smem + s * G1_STAGE); };
    auto sAl = [&](int s) { return (__nv_bfloat16*)(smem + s * G1_STAGE + 18432); };
    auto sBh = [&](int s) { return (__nv_bfloat16*)(smem + s * G1_STAGE + 36864); };
    auto sBl = [&](int s) { return (__nv_bfloat16*)(smem + s * G1_STAGE + 49920); };

    auto issue = [&](int k0_idx, int s) {
        const int k0 = k0_idx * 48;
        __nv_bfloat16 *ah = sAh(s), *al = sAl(s), *bh = sBh(s), *bl = sBl(s);
        for (int idx = tid; idx < 128 * 6; idx += 256) {
            int r = idx / 6, cb = (idx % 6) * 8;
            size_t go = (size_t)(row0 + r) * WIN + k0 + cb;
            cp16(&ah[r * G1_AST + cb], &g_a_hi[go]);
            cp16(&al[r * G1_AST + cb], &g_a_lo[go]);
        }
        for (int idx = tid; idx < 48 * 16; idx += 256) {
            int r = idx / 16, cb = (idx % 16) * 8;
            int gn = col0 + cb;
            bool ok = gn < WIN;
            size_t go = ok ? (size_t)(k0 + r) * WIN + gn : 0;
            cp16_pred(&bh[r * G1_BST + cb], &g_w1h[go], ok);
            cp16_pred(&bl[r * G1_BST + cb], &g_w1l[go], ok);
        }
    };

    float acc1[4][4][4], acc2[4][4][4];
#pragma unroll
    for (int i = 0; i < 4; i++)
#pragma unroll
        for (int j = 0; j < 4; j++)
#pragma unroll
            for (int k = 0; k < 4; k++) { acc1[i][j][k] = 0.0f; acc2[i][j][k] = 0.0f; }

    issue(0, 0);
    cp_commit();

    for (int it = 0; it < 7; it++) {
        const int s = it & 1;
        if (it < 6) {
            issue(it + 1, s ^ 1);
            cp_commit();
            cp_wait<1>();
        } else {
            cp_wait<0>();
        }
        __syncthreads();

        __nv_bfloat16 *ah_s = sAh(s), *al_s = sAl(s), *bh_s = sBh(s), *bl_s = sBl(s);
#pragma unroll
        for (int ks = 0; ks < 3; ks++) {
            unsigned bh[2][4], bl[2][4];
#pragma unroll
            for (int nf2 = 0; nf2 < 2; nf2++) {
                ldsm_x4t(bh[nf2], sm_u32(&bh_s[(ks * 16 + lrow) * G1_BST + wn * 32 + nf2 * 16 + lcol]));
                ldsm_x4t(bl[nf2], sm_u32(&bl_s[(ks * 16 + lrow) * G1_BST + wn * 32 + nf2 * 16 + lcol]));
            }
            unsigned ah[4][4], al[4][4];
#pragma unroll
            for (int mf = 0; mf < 4; mf++) {
                ldsm_x4(ah[mf], sm_u32(&ah_s[(wm * 64 + mf * 16 + lrow) * G1_AST + ks * 16 + lcol]));
                ldsm_x4(al[mf], sm_u32(&al_s[(wm * 64 + mf * 16 + lrow) * G1_AST + ks * 16 + lcol]));
            }
#pragma unroll
            for (int mf = 0; mf < 4; mf++) {
#pragma unroll
                for (int nf2 = 0; nf2 < 2; nf2++) {
#pragma unroll
                    for (int h = 0; h < 2; h++) {
                        int n8 = nf2 * 2 + h;
                        mma16816(acc1[mf][n8], ah[mf], bh[nf2][2 * h], bh[nf2][2 * h + 1]);
                        mma16816(acc2[mf][n8], al[mf], bh[nf2][2 * h], bh[nf2][2 * h + 1]);
                        mma16816(acc2[mf][n8], ah[mf], bl[nf2][2 * h], bl[nf2][2 * h + 1]);
                    }
                }
            }
        }
        __syncthreads();
    }

    const int group = lane >> 2, tig = lane & 3;
#pragma unroll
    for (int mf = 0; mf < 4; mf++) {
#pragma unroll
        for (int n8 = 0; n8 < 4; n8++) {
            int gc = col0 + wn * 32 + n8 * 8 + 2 * tig;
            if (gc >= WIN) continue;
            float b0 = bias[gc], b1 = bias[gc + 1];
            int r0 = row0 + wm * 64 + mf * 16 + group;
#pragma unroll
            for (int half = 0; half < 2; half++) {
                int gr = r0 + half * 8;
                float t0 = tanhf(acc1[mf][n8][2 * half] + acc2[mf][n8][2 * half] + b0);
                float t1 = tanhf(acc1[mf][n8][2 * half + 1] + acc2[mf][n8][2 * half + 1] + b1);
                __nv_bfloat16 h0, l0, h1, l1;
                split_bf16(t0, h0, l0);
                split_bf16(t1, h1, l1);
                size_t go = (size_t)gr * WIN + gc;
                *reinterpret_cast<__nv_bfloat162*>(&g_h_hi[go]) = __nv_bfloat162{h0, h1};
                *reinterpret_cast<__nv_bfloat162*>(&g_h_lo[go]) = __nv_bfloat162{l0, l1};
            }
        }
    }
}

// ---------------- GEMM2: out = hidden@W2 + b2, dual-acc, 2 CTAs/SM ----------------
#define G2_BST 72
__global__ void __launch_bounds__(256, 2)
gemm2_kernel(const float* __restrict__ bias, float* __restrict__ out) {
    extern __shared__ char smem[];
    const int tid = threadIdx.x;
    const int wid = tid >> 5, lane = tid & 31;
    const int row0 = blockIdx.x * 128;
    const int lrow = lane & 15, lcol = (lane >> 4) << 3;

    auto sAh = [&](int s) { return (__nv_bfloat16*)(smem + s * G2_STAGE); };
    auto sAl = [&](int s) { return (__nv_bfloat16*)(smem + s * G2_STAGE + 18432); };
    auto sBh = [&](int s) { return (__nv_bfloat16*)(smem + s * G2_STAGE + 36864); };
    auto sBl = [&](int s) { return (__nv_bfloat16*)(smem + s * G2_STAGE + 43776); };

    auto issue = [&](int k0_idx, int s) {
        const int k0 = k0_idx * 48;
        __nv_bfloat16 *ah = sAh(s), *al = sAl(s), *bh = sBh(s), *bl = sBl(s);
        for (int idx = tid; idx < 128 * 6; idx += 256) {
            int r = idx / 6, cb = (idx % 6) * 8;
            size_t go = (size_t)(row0 + r) * WIN + k0 + cb;
            cp16(&ah[r * G1_AST + cb], &g_h_hi[go]);
            cp16(&al[r * G1_AST + cb], &g_h_lo[go]);
        }
        for (int idx = tid; idx < 48 * 6; idx += 256) {
            int r = idx / 6, cb = (idx % 6) * 8;
            size_t go = (size_t)(k0 + r) * OUTSZ + cb;
            cp16(&bh[r * G2_BST + cb], &g_w2h[go]);
            cp16(&bl[r * G2_BST + cb], &g_w2l[go]);
        }
    };

    float acc1[6][4], acc2[6][4];
#pragma unroll
    for (int i = 0; i < 6; i++)
#pragma unroll
        for (int k = 0; k < 4; k++) { acc1[i][k] = 0.0f; acc2[i][k] = 0.0f; }

    issue(0, 0);
    cp_commit();

    for (int it = 0; it < 7; it++) {
        const int s = it & 1;
        if (it < 6) {
            issue(it + 1, s ^ 1);
            cp_commit();
            cp_wait<1>();
        } else {
            cp_wait<0>();
        }
        __syncthreads();

        __nv_bfloat16 *ah_s = sAh(s), *al_s = sAl(s), *bh_s = sBh(s), *bl_s = sBl(s);
#pragma unroll
        for (int ks = 0; ks < 3; ks++) {
            unsigned ah[4], al[4];
            ldsm_x4(ah, sm_u32(&ah_s[(wid * 16 + lrow) * G1_AST + ks * 16 + lcol]));
            ldsm_x4(al, sm_u32(&al_s[(wid * 16 + lrow) * G1_AST + ks * 16 + lcol]));
#pragma unroll
            for (int nf2 = 0; nf2 < 3; nf2++) {
                unsigned bh[4], bl[4];
                ldsm_x4t(bh, sm_u32(&bh_s[(ks * 16 + lrow) * G2_BST + nf2 * 16 + lcol]));
                ldsm_x4t(bl, sm_u32(&bl_s[(ks * 16 + lrow) * G2_BST + nf2 * 16 + lcol]));
#pragma unroll
                for (int h = 0; h < 2; h++) {
                    int n8 = nf2 * 2 + h;
                    mma16816(acc1[n8], ah, bh[2 * h], bh[2 * h + 1]);
                    mma16816(acc2[n8], al, bh[2 * h], bh[2 * h + 1]);
                    mma16816(acc2[n8], ah, bl[2 * h], bl[2 * h + 1]);
                }
            }
        }
        __syncthreads();
    }

    const int group = lane >> 2, tig = lane & 3;
#pragma unroll
    for (int n8 = 0; n8 < 6; n8++) {
        int gc = n8 * 8 + 2 * tig;
        float b0 = bias[gc], b1 = bias[gc + 1];
        int r0 = row0 + wid * 16 + group;
#pragma unroll
        for (int half = 0; half < 2; half++) {
            int gr = r0 + half * 8;
            if (gr < N_ROWS) {
                float2 v = make_float2(acc1[n8][2 * half] + acc2[n8][2 * half] + b0,
                                       acc1[n8][2 * half + 1] + acc2[n8][2 * half + 1] + b1);
                *reinterpret_cast<float2*>(&out[(size_t)gr * OUTSZ + gc]) = v;
            }
        }
    }
}

// ---------------- launch ----------------
extern "C" void kernel_launch(void* const* d_in, const int* in_sizes, int n_in,
                              void* d_out, int out_size) {
    const float* x           = (const float*)d_in[0];
    const float* lvl_coef    = (const float*)d_in[1];
    const float* seas_coef   = (const float*)d_in[2];
    const float* seas_params = (const float*)d_in[3];
    const float* W_tanh      = (const float*)d_in[4];
    const float* b_tanh      = (const float*)d_in[5];
    const float* W_out       = (const float*)d_in[6];
    const float* b_out       = (const float*)d_in[7];
    float* out = (float*)d_out;

    cudaFuncSetAttribute(gemm1_kernel, cudaFuncAttributeMaxDynamicSharedMemorySize, G1_SMEM);
    cudaFuncSetAttribute(gemm2_kernel, cudaFuncAttributeMaxDynamicSharedMemorySize, G2_SMEM);

    wsplit1_kernel<<<(WIN * WIN + 255) / 256, 256>>>(W_tanh);
    wsplit2_kernel<<<(WIN * OUTSZ + 255) / 256, 256>>>(W_out);
    {
        unsigned total = (unsigned)(M_PAD - N_ROWS) * WIN;
        zero_tail_kernel<<<(total / 2 + 255) / 256, 256>>>();
    }
    // fused scan+gen at launch index 3 (profiled by the harness ncu capture)
    fused_scan_gen_kernel<<<148, 1024>>>(x, lvl_coef, seas_coef, seas_params, out);
    {
        dim3 grid(M_PAD / 128, 3);
        gemm1_kernel<<<grid, 256, G1_SMEM>>>(b_tanh);
    }
    loss_kernel<<<1, 1024>>>(out);
    {
        dim3 grid(M_PAD / 128);
        gemm2_kernel<<<grid, 256, G2_SMEM>>>(b_out, out);
    }
    (void)in_sizes; (void)n_in; (void)out_size;
}

// round 16
// speedup vs baseline: 1.4957x; 1.4957x over previous
#include <cuda_runtime.h>
#include <cuda_bf16.h>
#include <math.h>

#define T_LEN 100000
#define WIN   336
#define OUTSZ 48
#define SEAS  168
#define N_ROWS (T_LEN - WIN - OUTSZ + 1)   // 99617
#define M_PAD  99712                        // 779 * 128
#define STD_NOISE 0.001f
#define LVP_F 50.0f
#define CHUNK 160
#define LPL 5
#define GROWS 24                            // rows per worker group

#define G1_STAGE 62976
#define G1_SMEM  (2 * G1_STAGE)
#define G2_STAGE 50688
#define G2_SMEM  (2 * G2_STAGE)

// ---------------- device scratch ----------------
__device__ float g_levels[T_LEN];
__device__ float g_llev[T_LEN];
__device__ float g_c[T_LEN];
__device__ unsigned g_progress;
__device__ __nv_bfloat16 g_a_hi[(size_t)M_PAD * WIN];
__device__ __nv_bfloat16 g_a_lo[(size_t)M_PAD * WIN];
__device__ __nv_bfloat16 g_h_hi[(size_t)M_PAD * WIN];
__device__ __nv_bfloat16 g_h_lo[(size_t)M_PAD * WIN];
__device__ __nv_bfloat16 g_w1h[WIN * WIN], g_w1l[WIN * WIN];
__device__ __nv_bfloat16 g_w2h[WIN * OUTSZ], g_w2l[WIN * OUTSZ];

// ---------------- compile-time threefry ----------------
struct TF2 { unsigned y0, y1; };
__host__ __device__ constexpr unsigned tf_rotl(unsigned x, int r) {
    return (x << r) | (x >> (32 - r));
}
__host__ __device__ constexpr TF2 tf2x32_const(unsigned k0, unsigned k1,
                                               unsigned x0, unsigned x1) {
    unsigned ks2 = 0x1BD11BDAu ^ k0 ^ k1;
    const int R[8] = {13, 15, 26, 6, 17, 29, 16, 24};
    x0 += k0; x1 += k1;
    for (int i = 0; i < 4; i++) { x0 += x1; x1 = tf_rotl(x1, R[i]); x1 ^= x0; }
    x0 += k1;  x1 += ks2 + 1u;
    for (int i = 4; i < 8; i++) { x0 += x1; x1 = tf_rotl(x1, R[i]); x1 ^= x0; }
    x0 += ks2; x1 += k0 + 2u;
    for (int i = 0; i < 4; i++) { x0 += x1; x1 = tf_rotl(x1, R[i]); x1 ^= x0; }
    x0 += k0;  x1 += k1 + 3u;
    for (int i = 4; i < 8; i++) { x0 += x1; x1 = tf_rotl(x1, R[i]); x1 ^= x0; }
    x0 += k1;  x1 += ks2 + 4u;
    for (int i = 0; i < 4; i++) { x0 += x1; x1 = tf_rotl(x1, R[i]); x1 ^= x0; }
    x0 += ks2; x1 += k0 + 5u;
    return TF2{x0, x1};
}

// ---------------- runtime threefry2x32 (JAX partitionable) ----------------
__device__ __forceinline__ void threefry2x32(unsigned k0, unsigned k1,
                                             unsigned x0, unsigned x1,
                                             unsigned& y0, unsigned& y1) {
    unsigned ks2 = 0x1BD11BDAu ^ k0 ^ k1;
#define TF_RND(r) { x0 += x1; x1 = (x1 << (r)) | (x1 >> (32 - (r))); x1 ^= x0; }
    x0 += k0; x1 += k1;
    TF_RND(13) TF_RND(15) TF_RND(26) TF_RND(6)
    x0 += k1;  x1 += ks2 + 1u;
    TF_RND(17) TF_RND(29) TF_RND(16) TF_RND(24)
    x0 += ks2; x1 += k0 + 2u;
    TF_RND(13) TF_RND(15) TF_RND(26) TF_RND(6)
    x0 += k0;  x1 += k1 + 3u;
    TF_RND(17) TF_RND(29) TF_RND(16) TF_RND(24)
    x0 += k1;  x1 += ks2 + 4u;
    TF_RND(13) TF_RND(15) TF_RND(26) TF_RND(6)
    x0 += ks2; x1 += k0 + 5u;
#undef TF_RND
    y0 = x0; y1 = x1;
}
__device__ __forceinline__ unsigned tf_bits32(unsigned k0, unsigned k1, unsigned i) {
    unsigned y0, y1;
    threefry2x32(k0, k1, 0u, i, y0, y1);
    return y0 ^ y1;
}

__device__ __forceinline__ float bits_to_normal(unsigned bits) {
    float f = __uint_as_float((bits >> 9) | 0x3f800000u) - 1.0f;
    const float LO = -0.99999994f;
    float u = fmaxf(LO, f * 2.0f + LO);
    float x = u;
    float w = -__logf(fmaf(-x, x, 1.0f));
    float p;
    if (w < 5.0f) {
        w -= 2.5f;
        p =              2.81022636e-08f;
        p = fmaf(p, w,   3.43273939e-07f);
        p = fmaf(p, w,  -3.5233877e-06f);
        p = fmaf(p, w,  -4.39150654e-06f);
        p = fmaf(p, w,   0.00021858087f);
        p = fmaf(p, w,  -0.00125372503f);
        p = fmaf(p, w,  -0.00417768164f);
        p = fmaf(p, w,   0.246640727f);
        p = fmaf(p, w,   1.50140941f);
    } else {
        w = sqrtf(w) - 3.0f;
        p =             -0.000200214257f;
        p = fmaf(p, w,   0.000100950558f);
        p = fmaf(p, w,   0.00134934322f);
        p = fmaf(p, w,  -0.00367342844f);
        p = fmaf(p, w,   0.00573950773f);
        p = fmaf(p, w,  -0.0076224613f);
        p = fmaf(p, w,   0.00943887047f);
        p = fmaf(p, w,   1.00167406f);
        p = fmaf(p, w,   2.83297682f);
    }
    return 1.41421356237f * (p * x);
}

// ---------------- split helper ----------------
__device__ __forceinline__ void split_bf16(float v, __nv_bfloat16& hi, __nv_bfloat16& lo) {
    hi = __float2bfloat16(v);
    lo = __float2bfloat16(v - __bfloat162float(hi));
}

// ---------------- weight splits ----------------
__global__ void wsplit1_kernel(const float* __restrict__ W1) {
    int i = blockIdx.x * blockDim.x + threadIdx.x;
    if (i < WIN * WIN) split_bf16(W1[i], g_w1h[i], g_w1l[i]);
}
__global__ void wsplit2_kernel(const float* __restrict__ W2) {
    int i = blockIdx.x * blockDim.x + threadIdx.x;
    if (i < WIN * OUTSZ) split_bf16(W2[i], g_w2h[i], g_w2l[i]);
}

// ---------------- zero A tail rows + reset progress ----------------
__global__ void zero_tail_kernel() {
    if (blockIdx.x == 0 && threadIdx.x == 0) g_progress = 0u;
    const unsigned start = (unsigned)N_ROWS * WIN;
    const unsigned total = (unsigned)M_PAD * WIN - start;
    unsigned i = 2u * (blockIdx.x * blockDim.x + threadIdx.x);
    if (i < total) {
        *reinterpret_cast<unsigned*>(&g_a_hi[start + i]) = 0u;
        *reinterpret_cast<unsigned*>(&g_a_lo[start + i]) = 0u;
    }
}

// ---------------- FUSED: scan (block 0) + gen inputs/labels (workers) ----------------
// Sync: producer publishes progress via volatile STORE after __threadfence;
// consumers poll with volatile LOADS (no atomics -> no L2 single-address ALU
// serialization, which is what killed round 14).
__global__ void __launch_bounds__(1024, 1)
fused_scan_gen_kernel(const float* __restrict__ x,
                      const float* __restrict__ lvl_coef,
                      const float* __restrict__ seas_coef,
                      const float* __restrict__ seas_params,
                      float* __restrict__ d_out) {
    if (blockIdx.x == 0) {
        if (threadIdx.x >= 32) return;
        __shared__ float ring[512];
        const int lane = threadIdx.x;
        const unsigned FULL = 0xFFFFFFFFu;
        for (int i = lane; i < SEAS; i += 32) ring[i] = expf(seas_params[i]);
        __syncwarp();
        if (lane == 0) ring[SEAS] = ring[0];
        __syncwarp();

        const float a = 1.0f / (1.0f + expf(-lvl_coef[0]));
        const float g = 1.0f / (1.0f + expf(-seas_coef[0]));
        const float b = 1.0f - a;
        const float omg = 1.0f - g;
        const float b5 = b * b * b * b * b;
        const float bl = __powf(b5, (float)lane);

        float level = x[0] / ring[0];
        if (lane == 0) {
            g_levels[0] = level;
            g_llev[0] = __logf(level);
            g_c[0] = __logf(x[0]) - __logf(ring[0]);
        }

        float xn[LPL];
        {
            const int base = 1 + lane * LPL;
#pragma unroll
            for (int j = 0; j < LPL; j++)
                xn[j] = (base + j < T_LEN) ? __ldg(&x[base + j]) : 1.0f;
        }

        int ck = 0;
        for (int t0 = 1; t0 < T_LEN; t0 += CHUNK) {
            const int base = t0 + lane * LPL;
            float xi[LPL];
#pragma unroll
            for (int j = 0; j < LPL; j++) xi[j] = xn[j];
            {
                const int nbase = t0 + CHUNK + lane * LPL;
#pragma unroll
                for (int j = 0; j < LPL; j++)
                    xn[j] = (nbase + j < T_LEN) ? __ldg(&x[nbase + j]) : 1.0f;
            }
            float se[LPL], c[LPL];
#pragma unroll
            for (int j = 0; j < LPL; j++) {
                int t = base + j;
                if (t < T_LEN) {
                    se[j] = ring[t & 511];
                    c[j]  = __fdividef(a * xi[j], se[j]);
                    g_c[t] = __logf(xi[j]) - __logf(se[j]);
                } else { se[j] = 1.0f; c[j] = 0.0f; }
            }
            float s = 0.0f;
#pragma unroll
            for (int j = 0; j < LPL; j++) s = fmaf(b, s, c[j]);
            float S = s;
            float m = b5;
#pragma unroll
            for (int off = 1; off < 32; off <<= 1) {
                float up = __shfl_up_sync(FULL, S, off);
                if (lane >= off) S = fmaf(m, up, S);
                m = m * m;
            }
            float Sprev = __shfl_up_sync(FULL, S, 1);
            if (lane == 0) Sprev = 0.0f;
            float lvl = fmaf(bl, level, Sprev);
#pragma unroll
            for (int j = 0; j < LPL; j++) {
                int t = base + j;
                if (t < T_LEN) {
                    lvl = fmaf(b, lvl, c[j]);
                    g_levels[t] = lvl;
                    g_llev[t] = __logf(lvl);
                    float ns = fmaf(omg, se[j], __fdividef(g * xi[j], lvl));
                    ring[(t + SEAS) & 511] = ns;
                }
            }
            level = __shfl_sync(FULL, lvl, 31);
            ck++;
            if ((ck & 1) == 0) {
                __threadfence();
                __syncwarp();
                if (lane == 0) {
                    unsigned done = (unsigned)min(t0 + CHUNK, T_LEN);
                    *(volatile unsigned*)&g_progress = done;   // plain release store
                }
                __syncwarp();
            } else {
                __syncwarp();
            }
        }
        __threadfence();
        __syncwarp();
        if (lane == 0) *(volatile unsigned*)&g_progress = (unsigned)T_LEN;
        return;
    }

    // ---------- consumers ----------
    constexpr TF2 K1 = tf2x32_const(0u, 1u, 0u, 0u);
    constexpr TF2 K2 = tf2x32_const(0u, 1u, 0u, 1u);
    const int nworkers = gridDim.x - 1;
    const int wrk = blockIdx.x - 1;
    const unsigned NGROUPS = (N_ROWS + GROWS - 1) / GROWS;
    float* labels = d_out + (size_t)N_ROWS * OUTSZ;

    for (unsigned gidx = wrk; gidx < NGROUPS; gidx += nworkers) {
        const unsigned n0 = gidx * GROWS;
        const unsigned n1 = min(n0 + GROWS, (unsigned)N_ROWS);
        const unsigned rows = n1 - n0;
        const unsigned needed = n1 - 1 + WIN + OUTSZ;   // <= T_LEN
        if (threadIdx.x == 0) {
            while (*(volatile unsigned*)&g_progress < needed) __nanosleep(400);
        }
        __syncthreads();

        // inputs: rows * 84 groups of 4 bf16 elements (data read via L2 to skip stale L1)
        const unsigned e4in = rows * (WIN / 4);
        for (unsigned i4 = threadIdx.x; i4 < e4in; i4 += 1024) {
            unsigned n = n0 + i4 / (WIN / 4);
            unsigned w = (i4 % (WIN / 4)) * 4;
            float llv = __ldcg(&g_llev[n + WIN]);
            unsigned ibase = n * WIN + w;
            __nv_bfloat16 hi[4], lo[4];
#pragma unroll
            for (int j = 0; j < 4; j++) {
                float z = bits_to_normal(tf_bits32(K1.y0, K1.y1, ibase + j));
                float v = __ldcg(&g_c[n + w + j]) - llv + STD_NOISE * z;
                split_bf16(v, hi[j], lo[j]);
            }
            *reinterpret_cast<__nv_bfloat162*>(&g_a_hi[ibase])     = __nv_bfloat162{hi[0], hi[1]};
            *reinterpret_cast<__nv_bfloat162*>(&g_a_hi[ibase + 2]) = __nv_bfloat162{hi[2], hi[3]};
            *reinterpret_cast<__nv_bfloat162*>(&g_a_lo[ibase])     = __nv_bfloat162{lo[0], lo[1]};
            *reinterpret_cast<__nv_bfloat162*>(&g_a_lo[ibase + 2]) = __nv_bfloat162{lo[2], lo[3]};
        }
        // labels: rows * 12 groups
        const unsigned e4lb = rows * (OUTSZ / 4);
        for (unsigned i4 = threadIdx.x; i4 < e4lb; i4 += 1024) {
            unsigned n = n0 + i4 / (OUTSZ / 4);
            unsigned o = (i4 % (OUTSZ / 4)) * 4;
            float llv = __ldcg(&g_llev[n + WIN]);
            unsigned ibase = n * OUTSZ + o;
            float v[4];
#pragma unroll
            for (int j = 0; j < 4; j++) {
                float z = bits_to_normal(tf_bits32(K2.y0, K2.y1, ibase + j));
                v[j] = __ldcg(&g_c[n + WIN + o + j]) - llv + STD_NOISE * z;
            }
            *reinterpret_cast<float4*>(&labels[ibase]) = make_float4(v[0], v[1], v[2], v[3]);
        }
    }
}

// ---------------- level variation loss (precise logf from levels) ----------------
__global__ void loss_kernel(float* __restrict__ d_out) {
    __shared__ double sh[1024];
    double acc = 0.0;
    for (int i = threadIdx.x; i < T_LEN - 2; i += 1024) {
        float l0 = logf(g_levels[i]);
        float l1 = logf(g_levels[i + 1]);
        float l2 = logf(g_levels[i + 2]);
        float d2 = (l2 - l1) - (l1 - l0);
        acc += (double)d2 * (double)d2;
    }
    sh[threadIdx.x] = acc;
    __syncthreads();
    for (int s = 512; s > 0; s >>= 1) {
        if (threadIdx.x < s) sh[threadIdx.x] += sh[threadIdx.x + s];
        __syncthreads();
    }
    if (threadIdx.x == 0)
        d_out[2 * (size_t)N_ROWS * OUTSZ] = (float)(sh[0] / (double)(T_LEN - 2) * (double)LVP_F);
}

// ---------------- mma / cp.async helpers ----------------
__device__ __forceinline__ unsigned sm_u32(const void* p) {
    return (unsigned)__cvta_generic_to_shared(p);
}
__device__ __forceinline__ void ldsm_x4(unsigned* d, unsigned addr) {
    asm volatile("ldmatrix.sync.aligned.m8n8.x4.shared.b16 {%0,%1,%2,%3}, [%4];"
                 : "=r"(d[0]), "=r"(d[1]), "=r"(d[2]), "=r"(d[3]) : "r"(addr));
}
__device__ __forceinline__ void ldsm_x4t(unsigned* d, unsigned addr) {
    asm volatile("ldmatrix.sync.aligned.m8n8.x4.trans.shared.b16 {%0,%1,%2,%3}, [%4];"
                 : "=r"(d[0]), "=r"(d[1]), "=r"(d[2]), "=r"(d[3]) : "r"(addr));
}
__device__ __forceinline__ void mma16816(float* c, const unsigned* a, unsigned b0, unsigned b1) {
    asm volatile("mma.sync.aligned.m16n8k16.row.col.f32.bf16.bf16.f32 "
                 "{%0,%1,%2,%3}, {%4,%5,%6,%7}, {%8,%9}, {%0,%1,%2,%3};"
                 : "+f"(c[0]), "+f"(c[1]), "+f"(c[2]), "+f"(c[3])
                 : "r"(a[0]), "r"(a[1]), "r"(a[2]), "r"(a[3]), "r"(b0), "r"(b1));
}
__device__ __forceinline__ void cp16(void* s, const void* g) {
    asm volatile("cp.async.cg.shared.global [%0], [%1], 16;"
                 :: "r"(sm_u32(s)), "l"(g));
}
__device__ __forceinline__ void cp16_pred(void* s, const void* g, bool ok) {
    int sz = ok ? 16 : 0;
    asm volatile("cp.async.cg.shared.global [%0], [%1], 16, %2;"
                 :: "r"(sm_u32(s)), "l"(g), "r"(sz));
}
__device__ __forceinline__ void cp_commit() {
    asm volatile("cp.async.commit_group;");
}
template<int N>
__device__ __forceinline__ void cp_wait() {
    asm volatile("cp.async.wait_group %0;" :: "n"(N));
}

// ---------------- GEMM1: dual-accumulator 3-term bf16, 2-stage cp.async ----------
#define G1_AST 72
#define G1_BST 136
__global__ void __launch_bounds__(256, 1)
gemm1_kernel(const float* __restrict__ bias) {
    extern __shared__ char smem[];
    const int tid = threadIdx.x;
    const int wid = tid >> 5, lane = tid & 31;
    const int wm = wid >> 2, wn = wid & 3;
    const int row0 = blockIdx.x * 128;
    const int col0 = blockIdx.y * 128;
    const int lrow = lane & 15, lcol = (lane >> 4) << 3;

    auto sAh = [&](int s) { return (__nv_bfloat16*)(smem + s * G1_STAGE); };
    auto sAl = [&](int s) { return (__nv_bfloat16*)(smem + s * G1_STAGE + 18432); };
    auto sBh = [&](int s) { return (__nv_bfloat16*)(smem + s * G1_STAGE + 36864); };
    auto sBl = [&](int s) { return (__nv_bfloat16*)(smem + s * G1_STAGE + 49920); };

    auto issue = [&](int k0_idx, int s) {
        const int k0 = k0_idx * 48;
        __nv_bfloat16 *ah = sAh(s), *al = sAl(s), *bh = sBh(s), *bl = sBl(s);
        for (int idx = tid; idx < 128 * 6; idx += 256) {
            int r = idx / 6, cb = (idx % 6) * 8;
            size_t go = (size_t)(row0 + r) * WIN + k0 + cb;
            cp16(&ah[r * G1_AST + cb], &g_a_hi[go]);
            cp16(&al[r * G1_AST + cb], &g_a_lo[go]);
        }
        for (int idx = tid; idx < 48 * 16; idx += 256) {
            int r = idx / 16, cb = (idx % 16) * 8;
            int gn = col0 + cb;
            bool ok = gn < WIN;
            size_t go = ok ? (size_t)(k0 + r) * WIN + gn : 0;
            cp16_pred(&bh[r * G1_BST + cb], &g_w1h[go], ok);
            cp16_pred(&bl[r * G1_BST + cb], &g_w1l[go], ok);
        }
    };

    float acc1[4][4][4], acc2[4][4][4];
#pragma unroll
    for (int i = 0; i < 4; i++)
#pragma unroll
        for (int j = 0; j < 4; j++)
#pragma unroll
            for (int k = 0; k < 4; k++) { acc1[i][j][k] = 0.0f; acc2[i][j][k] = 0.0f; }

    issue(0, 0);
    cp_commit();

    for (int it = 0; it < 7; it++) {
        const int s = it & 1;
        if (it < 6) {
            issue(it + 1, s ^ 1);
            cp_commit();
            cp_wait<1>();
        } else {
            cp_wait<0>();
        }
        __syncthreads();

        __nv_bfloat16 *ah_s = sAh(s), *al_s = sAl(s), *bh_s = sBh(s), *bl_s = sBl(s);
#pragma unroll
        for (int ks = 0; ks < 3; ks++) {
            unsigned bh[2][4], bl[2][4];
#pragma unroll
            for (int nf2 = 0; nf2 < 2; nf2++) {
                ldsm_x4t(bh[nf2], sm_u32(&bh_s[(ks * 16 + lrow) * G1_BST + wn * 32 + nf2 * 16 + lcol]));
                ldsm_x4t(bl[nf2], sm_u32(&bl_s[(ks * 16 + lrow) * G1_BST + wn * 32 + nf2 * 16 + lcol]));
            }
            unsigned ah[4][4], al[4][4];
#pragma unroll
            for (int mf = 0; mf < 4; mf++) {
                ldsm_x4(ah[mf], sm_u32(&ah_s[(wm * 64 + mf * 16 + lrow) * G1_AST + ks * 16 + lcol]));
                ldsm_x4(al[mf], sm_u32(&al_s[(wm * 64 + mf * 16 + lrow) * G1_AST + ks * 16 + lcol]));
            }
#pragma unroll
            for (int mf = 0; mf < 4; mf++) {
#pragma unroll
                for (int nf2 = 0; nf2 < 2; nf2++) {
#pragma unroll
                    for (int h = 0; h < 2; h++) {
                        int n8 = nf2 * 2 + h;
                        mma16816(acc1[mf][n8], ah[mf], bh[nf2][2 * h], bh[nf2][2 * h + 1]);
                        mma16816(acc2[mf][n8], al[mf], bh[nf2][2 * h], bh[nf2][2 * h + 1]);
                        mma16816(acc2[mf][n8], ah[mf], bl[nf2][2 * h], bl[nf2][2 * h + 1]);
                    }
                }
            }
        }
        __syncthreads();
    }

    const int group = lane >> 2, tig = lane & 3;
#pragma unroll
    for (int mf = 0; mf < 4; mf++) {
#pragma unroll
        for (int n8 = 0; n8 < 4; n8++) {
            int gc = col0 + wn * 32 + n8 * 8 + 2 * tig;
            if (gc >= WIN) continue;
            float b0 = bias[gc], b1 = bias[gc + 1];
            int r0 = row0 + wm * 64 + mf * 16 + group;
#pragma unroll
            for (int half = 0; half < 2; half++) {
                int gr = r0 + half * 8;
                float t0 = tanhf(acc1[mf][n8][2 * half] + acc2[mf][n8][2 * half] + b0);
                float t1 = tanhf(acc1[mf][n8][2 * half + 1] + acc2[mf][n8][2 * half + 1] + b1);
                __nv_bfloat16 h0, l0, h1, l1;
                split_bf16(t0, h0, l0);
                split_bf16(t1, h1, l1);
                size_t go = (size_t)gr * WIN + gc;
                *reinterpret_cast<__nv_bfloat162*>(&g_h_hi[go]) = __nv_bfloat162{h0, h1};
                *reinterpret_cast<__nv_bfloat162*>(&g_h_lo[go]) = __nv_bfloat162{l0, l1};
            }
        }
    }
}

// ---------------- GEMM2: out = hidden@W2 + b2, dual-acc, 2 CTAs/SM ----------------
#define G2_BST 72
__global__ void __launch_bounds__(256, 2)
gemm2_kernel(const float* __restrict__ bias, float* __restrict__ out) {
    extern __shared__ char smem[];
    const int tid = threadIdx.x;
    const int wid = tid >> 5, lane = tid & 31;
    const int row0 = blockIdx.x * 128;
    const int lrow = lane & 15, lcol = (lane >> 4) << 3;

    auto sAh = [&](int s) { return (__nv_bfloat16*)(smem + s * G2_STAGE); };
    auto sAl = [&](int s) { return (__nv_bfloat16*)(smem + s * G2_STAGE + 18432); };
    auto sBh = [&](int s) { return (__nv_bfloat16*)(smem + s * G2_STAGE + 36864); };
    auto sBl = [&](int s) { return (__nv_bfloat16*)(smem + s * G2_STAGE + 43776); };

    auto issue = [&](int k0_idx, int s) {
        const int k0 = k0_idx * 48;
        __nv_bfloat16 *ah = sAh(s), *al = sAl(s), *bh = sBh(s), *bl = sBl(s);
        for (int idx = tid; idx < 128 * 6; idx += 256) {
            int r = idx / 6, cb = (idx % 6) * 8;
            size_t go = (size_t)(row0 + r) * WIN + k0 + cb;
            cp16(&ah[r * G1_AST + cb], &g_h_hi[go]);
            cp16(&al[r * G1_AST + cb], &g_h_lo[go]);
        }
        for (int idx = tid; idx < 48 * 6; idx += 256) {
            int r = idx / 6, cb = (idx % 6) * 8;
            size_t go = (size_t)(k0 + r) * OUTSZ + cb;
            cp16(&bh[r * G2_BST + cb], &g_w2h[go]);
            cp16(&bl[r * G2_BST + cb], &g_w2l[go]);
        }
    };

    float acc1[6][4], acc2[6][4];
#pragma unroll
    for (int i = 0; i < 6; i++)
#pragma unroll
        for (int k = 0; k < 4; k++) { acc1[i][k] = 0.0f; acc2[i][k] = 0.0f; }

    issue(0, 0);
    cp_commit();

    for (int it = 0; it < 7; it++) {
        const int s = it & 1;
        if (it < 6) {
            issue(it + 1, s ^ 1);
            cp_commit();
            cp_wait<1>();
        } else {
            cp_wait<0>();
        }
        __syncthreads();

        __nv_bfloat16 *ah_s = sAh(s), *al_s = sAl(s), *bh_s = sBh(s), *bl_s = sBl(s);
#pragma unroll
        for (int ks = 0; ks < 3; ks++) {
            unsigned ah[4], al[4];
            ldsm_x4(ah, sm_u32(&ah_s[(wid * 16 + lrow) * G1_AST + ks * 16 + lcol]));
            ldsm_x4(al, sm_u32(&al_s[(wid * 16 + lrow) * G1_AST + ks * 16 + lcol]));
#pragma unroll
            for (int nf2 = 0; nf2 < 3; nf2++) {
                unsigned bh[4], bl[4];
                ldsm_x4t(bh, sm_u32(&bh_s[(ks * 16 + lrow) * G2_BST + nf2 * 16 + lcol]));
                ldsm_x4t(bl, sm_u32(&bl_s[(ks * 16 + lrow) * G2_BST + nf2 * 16 + lcol]));
#pragma unroll
                for (int h = 0; h < 2; h++) {
                    int n8 = nf2 * 2 + h;
                    mma16816(acc1[n8], ah, bh[2 * h], bh[2 * h + 1]);
                    mma16816(acc2[n8], al, bh[2 * h], bh[2 * h + 1]);
                    mma16816(acc2[n8], ah, bl[2 * h], bl[2 * h + 1]);
                }
            }
        }
        __syncthreads();
    }

    const int group = lane >> 2, tig = lane & 3;
#pragma unroll
    for (int n8 = 0; n8 < 6; n8++) {
        int gc = n8 * 8 + 2 * tig;
        float b0 = bias[gc], b1 = bias[gc + 1];
        int r0 = row0 + wid * 16 + group;
#pragma unroll
        for (int half = 0; half < 2; half++) {
            int gr = r0 + half * 8;
            if (gr < N_ROWS) {
                float2 v = make_float2(acc1[n8][2 * half] + acc2[n8][2 * half] + b0,
                                       acc1[n8][2 * half + 1] + acc2[n8][2 * half + 1] + b1);
                *reinterpret_cast<float2*>(&out[(size_t)gr * OUTSZ + gc]) = v;
            }
        }
    }
}

// ---------------- launch ----------------
extern "C" void kernel_launch(void* const* d_in, const int* in_sizes, int n_in,
                              void* d_out, int out_size) {
    const float* x           = (const float*)d_in[0];
    const float* lvl_coef    = (const float*)d_in[1];
    const float* seas_coef   = (const float*)d_in[2];
    const float* seas_params = (const float*)d_in[3];
    const float* W_tanh      = (const float*)d_in[4];
    const float* b_tanh      = (const float*)d_in[5];
    const float* W_out       = (const float*)d_in[6];
    const float* b_out       = (const float*)d_in[7];
    float* out = (float*)d_out;

    cudaFuncSetAttribute(gemm1_kernel, cudaFuncAttributeMaxDynamicSharedMemorySize, G1_SMEM);
    cudaFuncSetAttribute(gemm2_kernel, cudaFuncAttributeMaxDynamicSharedMemorySize, G2_SMEM);

    wsplit1_kernel<<<(WIN * WIN + 255) / 256, 256>>>(W_tanh);
    wsplit2_kernel<<<(WIN * OUTSZ + 255) / 256, 256>>>(W_out);
    {
        unsigned total = (unsigned)(M_PAD - N_ROWS) * WIN;
        zero_tail_kernel<<<(total / 2 + 255) / 256, 256>>>();
    }
    // fused scan+gen at launch index 3 (profiled by the harness ncu capture)
    fused_scan_gen_kernel<<<148, 1024>>>(x, lvl_coef, seas_coef, seas_params, out);
    {
        dim3 grid(M_PAD / 128, 3);
        gemm1_kernel<<<grid, 256, G1_SMEM>>>(b_tanh);
    }
    loss_kernel<<<1, 1024>>>(out);
    {
        dim3 grid(M_PAD / 128);
        gemm2_kernel<<<grid, 256, G2_SMEM>>>(b_out, out);
    }
    (void)in_sizes; (void)n_in; (void)out_size;
}

// round 17
// speedup vs baseline: 1.6457x; 1.1003x over previous
#include <cuda_runtime.h>
#include <cuda_bf16.h>
#include <math.h>

#define T_LEN 100000
#define WIN   336
#define OUTSZ 48
#define SEAS  168
#define N_ROWS (T_LEN - WIN - OUTSZ + 1)   // 99617
#define M_PAD  99712                        // 779 * 128
#define STD_NOISE 0.001f
#define LVP_F 50.0f
#define CHUNK 160
#define LPL 5
#define GROWS 24                            // rows per worker group

#define G1_STAGE 62976
#define G1_SMEM  (2 * G1_STAGE)
#define G2_STAGE 50688
#define G2_SMEM  (2 * G2_STAGE)

// ---------------- device scratch ----------------
__device__ float g_levels[T_LEN];
__device__ float g_llev[T_LEN];
__device__ float g_c[T_LEN];
__device__ unsigned g_progress;
__device__ __nv_bfloat16 g_a_hi[(size_t)M_PAD * WIN];
__device__ __nv_bfloat16 g_a_lo[(size_t)M_PAD * WIN];
__device__ __nv_bfloat16 g_h_hi[(size_t)M_PAD * WIN];
__device__ __nv_bfloat16 g_h_lo[(size_t)M_PAD * WIN];
__device__ __nv_bfloat16 g_w1h[WIN * WIN], g_w1l[WIN * WIN];
__device__ __nv_bfloat16 g_w2h[WIN * OUTSZ], g_w2l[WIN * OUTSZ];

// ---------------- compile-time threefry ----------------
struct TF2 { unsigned y0, y1; };
__host__ __device__ constexpr unsigned tf_rotl(unsigned x, int r) {
    return (x << r) | (x >> (32 - r));
}
__host__ __device__ constexpr TF2 tf2x32_const(unsigned k0, unsigned k1,
                                               unsigned x0, unsigned x1) {
    unsigned ks2 = 0x1BD11BDAu ^ k0 ^ k1;
    const int R[8] = {13, 15, 26, 6, 17, 29, 16, 24};
    x0 += k0; x1 += k1;
    for (int i = 0; i < 4; i++) { x0 += x1; x1 = tf_rotl(x1, R[i]); x1 ^= x0; }
    x0 += k1;  x1 += ks2 + 1u;
    for (int i = 4; i < 8; i++) { x0 += x1; x1 = tf_rotl(x1, R[i]); x1 ^= x0; }
    x0 += ks2; x1 += k0 + 2u;
    for (int i = 0; i < 4; i++) { x0 += x1; x1 = tf_rotl(x1, R[i]); x1 ^= x0; }
    x0 += k0;  x1 += k1 + 3u;
    for (int i = 4; i < 8; i++) { x0 += x1; x1 = tf_rotl(x1, R[i]); x1 ^= x0; }
    x0 += k1;  x1 += ks2 + 4u;
    for (int i = 0; i < 4; i++) { x0 += x1; x1 = tf_rotl(x1, R[i]); x1 ^= x0; }
    x0 += ks2; x1 += k0 + 5u;
    return TF2{x0, x1};
}

// ---------------- runtime threefry2x32 (JAX partitionable) ----------------
__device__ __forceinline__ void threefry2x32(unsigned k0, unsigned k1,
                                             unsigned x0, unsigned x1,
                                             unsigned& y0, unsigned& y1) {
    unsigned ks2 = 0x1BD11BDAu ^ k0 ^ k1;
#define TF_RND(r) { x0 += x1; x1 = (x1 << (r)) | (x1 >> (32 - (r))); x1 ^= x0; }
    x0 += k0; x1 += k1;
    TF_RND(13) TF_RND(15) TF_RND(26) TF_RND(6)
    x0 += k1;  x1 += ks2 + 1u;
    TF_RND(17) TF_RND(29) TF_RND(16) TF_RND(24)
    x0 += ks2; x1 += k0 + 2u;
    TF_RND(13) TF_RND(15) TF_RND(26) TF_RND(6)
    x0 += k0;  x1 += k1 + 3u;
    TF_RND(17) TF_RND(29) TF_RND(16) TF_RND(24)
    x0 += k1;  x1 += ks2 + 4u;
    TF_RND(13) TF_RND(15) TF_RND(26) TF_RND(6)
    x0 += ks2; x1 += k0 + 5u;
#undef TF_RND
    y0 = x0; y1 = x1;
}
__device__ __forceinline__ unsigned tf_bits32(unsigned k0, unsigned k1, unsigned i) {
    unsigned y0, y1;
    threefry2x32(k0, k1, 0u, i, y0, y1);
    return y0 ^ y1;
}

__device__ __forceinline__ float bits_to_normal(unsigned bits) {
    float f = __uint_as_float((bits >> 9) | 0x3f800000u) - 1.0f;
    const float LO = -0.99999994f;
    float u = fmaxf(LO, f * 2.0f + LO);
    float x = u;
    float w = -__logf(fmaf(-x, x, 1.0f));
    float p;
    if (w < 5.0f) {
        w -= 2.5f;
        p =              2.81022636e-08f;
        p = fmaf(p, w,   3.43273939e-07f);
        p = fmaf(p, w,  -3.5233877e-06f);
        p = fmaf(p, w,  -4.39150654e-06f);
        p = fmaf(p, w,   0.00021858087f);
        p = fmaf(p, w,  -0.00125372503f);
        p = fmaf(p, w,  -0.00417768164f);
        p = fmaf(p, w,   0.246640727f);
        p = fmaf(p, w,   1.50140941f);
    } else {
        w = sqrtf(w) - 3.0f;
        p =             -0.000200214257f;
        p = fmaf(p, w,   0.000100950558f);
        p = fmaf(p, w,   0.00134934322f);
        p = fmaf(p, w,  -0.00367342844f);
        p = fmaf(p, w,   0.00573950773f);
        p = fmaf(p, w,  -0.0076224613f);
        p = fmaf(p, w,   0.00943887047f);
        p = fmaf(p, w,   1.00167406f);
        p = fmaf(p, w,   2.83297682f);
    }
    return 1.41421356237f * (p * x);
}

// ---------------- split helper ----------------
__device__ __forceinline__ void split_bf16(float v, __nv_bfloat16& hi, __nv_bfloat16& lo) {
    hi = __float2bfloat16(v);
    lo = __float2bfloat16(v - __bfloat162float(hi));
}

// ---------------- weight splits ----------------
__global__ void wsplit1_kernel(const float* __restrict__ W1) {
    int i = blockIdx.x * blockDim.x + threadIdx.x;
    if (i < WIN * WIN) split_bf16(W1[i], g_w1h[i], g_w1l[i]);
}
__global__ void wsplit2_kernel(const float* __restrict__ W2) {
    int i = blockIdx.x * blockDim.x + threadIdx.x;
    if (i < WIN * OUTSZ) split_bf16(W2[i], g_w2h[i], g_w2l[i]);
}

// ---------------- zero A tail rows + reset progress ----------------
__global__ void zero_tail_kernel() {
    if (blockIdx.x == 0 && threadIdx.x == 0) g_progress = 0u;
    const unsigned start = (unsigned)N_ROWS * WIN;
    const unsigned total = (unsigned)M_PAD * WIN - start;
    unsigned i = 2u * (blockIdx.x * blockDim.x + threadIdx.x);
    if (i < total) {
        *reinterpret_cast<unsigned*>(&g_a_hi[start + i]) = 0u;
        *reinterpret_cast<unsigned*>(&g_a_lo[start + i]) = 0u;
    }
}

// ---------------- FUSED: scan (block 0) + gen inputs/labels (workers) ----------------
// Publish cadence = every 8 chunks: the producer-side __threadfence (which
// drains outstanding STGs through write queues shared with worker traffic)
// was stretching the scan by ~200us at every-2-chunk cadence.
__global__ void __launch_bounds__(1024, 1)
fused_scan_gen_kernel(const float* __restrict__ x,
                      const float* __restrict__ lvl_coef,
                      const float* __restrict__ seas_coef,
                      const float* __restrict__ seas_params,
                      float* __restrict__ d_out) {
    if (blockIdx.x == 0) {
        if (threadIdx.x >= 32) return;
        __shared__ float ring[512];
        const int lane = threadIdx.x;
        const unsigned FULL = 0xFFFFFFFFu;
        for (int i = lane; i < SEAS; i += 32) ring[i] = expf(seas_params[i]);
        __syncwarp();
        if (lane == 0) ring[SEAS] = ring[0];
        __syncwarp();

        const float a = 1.0f / (1.0f + expf(-lvl_coef[0]));
        const float g = 1.0f / (1.0f + expf(-seas_coef[0]));
        const float b = 1.0f - a;
        const float omg = 1.0f - g;
        const float b5 = b * b * b * b * b;
        const float bl = __powf(b5, (float)lane);

        float level = x[0] / ring[0];
        if (lane == 0) {
            g_levels[0] = level;
            g_llev[0] = __logf(level);
            g_c[0] = __logf(x[0]) - __logf(ring[0]);
        }

        float xn[LPL];
        {
            const int base = 1 + lane * LPL;
#pragma unroll
            for (int j = 0; j < LPL; j++)
                xn[j] = (base + j < T_LEN) ? __ldg(&x[base + j]) : 1.0f;
        }

        int ck = 0;
        for (int t0 = 1; t0 < T_LEN; t0 += CHUNK) {
            const int base = t0 + lane * LPL;
            float xi[LPL];
#pragma unroll
            for (int j = 0; j < LPL; j++) xi[j] = xn[j];
            {
                const int nbase = t0 + CHUNK + lane * LPL;
#pragma unroll
                for (int j = 0; j < LPL; j++)
                    xn[j] = (nbase + j < T_LEN) ? __ldg(&x[nbase + j]) : 1.0f;
            }
            float se[LPL], c[LPL];
#pragma unroll
            for (int j = 0; j < LPL; j++) {
                int t = base + j;
                if (t < T_LEN) {
                    se[j] = ring[t & 511];
                    c[j]  = __fdividef(a * xi[j], se[j]);
                    g_c[t] = __logf(xi[j]) - __logf(se[j]);
                } else { se[j] = 1.0f; c[j] = 0.0f; }
            }
            float s = 0.0f;
#pragma unroll
            for (int j = 0; j < LPL; j++) s = fmaf(b, s, c[j]);
            float S = s;
            float m = b5;
#pragma unroll
            for (int off = 1; off < 32; off <<= 1) {
                float up = __shfl_up_sync(FULL, S, off);
                if (lane >= off) S = fmaf(m, up, S);
                m = m * m;
            }
            float Sprev = __shfl_up_sync(FULL, S, 1);
            if (lane == 0) Sprev = 0.0f;
            float lvl = fmaf(bl, level, Sprev);
#pragma unroll
            for (int j = 0; j < LPL; j++) {
                int t = base + j;
                if (t < T_LEN) {
                    lvl = fmaf(b, lvl, c[j]);
                    g_levels[t] = lvl;
                    g_llev[t] = __logf(lvl);
                    float ns = fmaf(omg, se[j], __fdividef(g * xi[j], lvl));
                    ring[(t + SEAS) & 511] = ns;
                }
            }
            level = __shfl_sync(FULL, lvl, 31);
            ck++;
            if ((ck & 7) == 0) {
                __threadfence();
                __syncwarp();
                if (lane == 0) {
                    unsigned done = (unsigned)min(t0 + CHUNK, T_LEN);
                    *(volatile unsigned*)&g_progress = done;
                }
                __syncwarp();
            } else {
                __syncwarp();
            }
        }
        __threadfence();
        __syncwarp();
        if (lane == 0) *(volatile unsigned*)&g_progress = (unsigned)T_LEN;
        return;
    }

    // ---------- consumers ----------
    constexpr TF2 K1 = tf2x32_const(0u, 1u, 0u, 0u);
    constexpr TF2 K2 = tf2x32_const(0u, 1u, 0u, 1u);
    const int nworkers = gridDim.x - 1;
    const int wrk = blockIdx.x - 1;
    const unsigned NGROUPS = (N_ROWS + GROWS - 1) / GROWS;
    float* labels = d_out + (size_t)N_ROWS * OUTSZ;

    for (unsigned gidx = wrk; gidx < NGROUPS; gidx += nworkers) {
        const unsigned n0 = gidx * GROWS;
        const unsigned n1 = min(n0 + GROWS, (unsigned)N_ROWS);
        const unsigned rows = n1 - n0;
        const unsigned needed = n1 - 1 + WIN + OUTSZ;   // <= T_LEN
        if (threadIdx.x == 0) {
            while (*(volatile unsigned*)&g_progress < needed) __nanosleep(800);
        }
        __syncthreads();

        const unsigned e4in = rows * (WIN / 4);
        for (unsigned i4 = threadIdx.x; i4 < e4in; i4 += 1024) {
            unsigned n = n0 + i4 / (WIN / 4);
            unsigned w = (i4 % (WIN / 4)) * 4;
            float llv = __ldcg(&g_llev[n + WIN]);
            unsigned ibase = n * WIN + w;
            __nv_bfloat16 hi[4], lo[4];
#pragma unroll
            for (int j = 0; j < 4; j++) {
                float z = bits_to_normal(tf_bits32(K1.y0, K1.y1, ibase + j));
                float v = __ldcg(&g_c[n + w + j]) - llv + STD_NOISE * z;
                split_bf16(v, hi[j], lo[j]);
            }
            *reinterpret_cast<__nv_bfloat162*>(&g_a_hi[ibase])     = __nv_bfloat162{hi[0], hi[1]};
            *reinterpret_cast<__nv_bfloat162*>(&g_a_hi[ibase + 2]) = __nv_bfloat162{hi[2], hi[3]};
            *reinterpret_cast<__nv_bfloat162*>(&g_a_lo[ibase])     = __nv_bfloat162{lo[0], lo[1]};
            *reinterpret_cast<__nv_bfloat162*>(&g_a_lo[ibase + 2]) = __nv_bfloat162{lo[2], lo[3]};
        }
        const unsigned e4lb = rows * (OUTSZ / 4);
        for (unsigned i4 = threadIdx.x; i4 < e4lb; i4 += 1024) {
            unsigned n = n0 + i4 / (OUTSZ / 4);
            unsigned o = (i4 % (OUTSZ / 4)) * 4;
            float llv = __ldcg(&g_llev[n + WIN]);
            unsigned ibase = n * OUTSZ + o;
            float v[4];
#pragma unroll
            for (int j = 0; j < 4; j++) {
                float z = bits_to_normal(tf_bits32(K2.y0, K2.y1, ibase + j));
                v[j] = __ldcg(&g_c[n + WIN + o + j]) - llv + STD_NOISE * z;
            }
            *reinterpret_cast<float4*>(&labels[ibase]) = make_float4(v[0], v[1], v[2], v[3]);
        }
    }
}

// ---------------- level variation loss (precise logf from levels) ----------------
__global__ void loss_kernel(float* __restrict__ d_out) {
    __shared__ double sh[1024];
    double acc = 0.0;
    for (int i = threadIdx.x; i < T_LEN - 2; i += 1024) {
        float l0 = logf(g_levels[i]);
        float l1 = logf(g_levels[i + 1]);
        float l2 = logf(g_levels[i + 2]);
        float d2 = (l2 - l1) - (l1 - l0);
        acc += (double)d2 * (double)d2;
    }
    sh[threadIdx.x] = acc;
    __syncthreads();
    for (int s = 512; s > 0; s >>= 1) {
        if (threadIdx.x < s) sh[threadIdx.x] += sh[threadIdx.x + s];
        __syncthreads();
    }
    if (threadIdx.x == 0)
        d_out[2 * (size_t)N_ROWS * OUTSZ] = (float)(sh[0] / (double)(T_LEN - 2) * (double)LVP_F);
}

// ---------------- mma / cp.async helpers ----------------
__device__ __forceinline__ unsigned sm_u32(const void* p) {
    return (unsigned)__cvta_generic_to_shared(p);
}
__device__ __forceinline__ void ldsm_x4(unsigned* d, unsigned addr) {
    asm volatile("ldmatrix.sync.aligned.m8n8.x4.shared.b16 {%0,%1,%2,%3}, [%4];"
                 : "=r"(d[0]), "=r"(d[1]), "=r"(d[2]), "=r"(d[3]) : "r"(addr));
}
__device__ __forceinline__ void ldsm_x4t(unsigned* d, unsigned addr) {
    asm volatile("ldmatrix.sync.aligned.m8n8.x4.trans.shared.b16 {%0,%1,%2,%3}, [%4];"
                 : "=r"(d[0]), "=r"(d[1]), "=r"(d[2]), "=r"(d[3]) : "r"(addr));
}
__device__ __forceinline__ void mma16816(float* c, const unsigned* a, unsigned b0, unsigned b1) {
    asm volatile("mma.sync.aligned.m16n8k16.row.col.f32.bf16.bf16.f32 "
                 "{%0,%1,%2,%3}, {%4,%5,%6,%7}, {%8,%9}, {%0,%1,%2,%3};"
                 : "+f"(c[0]), "+f"(c[1]), "+f"(c[2]), "+f"(c[3])
                 : "r"(a[0]), "r"(a[1]), "r"(a[2]), "r"(a[3]), "r"(b0), "r"(b1));
}
__device__ __forceinline__ void cp16(void* s, const void* g) {
    asm volatile("cp.async.cg.shared.global [%0], [%1], 16;"
                 :: "r"(sm_u32(s)), "l"(g));
}
__device__ __forceinline__ void cp16_pred(void* s, const void* g, bool ok) {
    int sz = ok ? 16 : 0;
    asm volatile("cp.async.cg.shared.global [%0], [%1], 16, %2;"
                 :: "r"(sm_u32(s)), "l"(g), "r"(sz));
}
__device__ __forceinline__ void cp_commit() {
    asm volatile("cp.async.commit_group;");
}
template<int N>
__device__ __forceinline__ void cp_wait() {
    asm volatile("cp.async.wait_group %0;" :: "n"(N));
}

// ---------------- GEMM1: dual-accumulator 3-term bf16, 2-stage cp.async ----------
#define G1_AST 72
#define G1_BST 136
__global__ void __launch_bounds__(256, 1)
gemm1_kernel(const float* __restrict__ bias) {
    extern __shared__ char smem[];
    const int tid = threadIdx.x;
    const int wid = tid >> 5, lane = tid & 31;
    const int wm = wid >> 2, wn = wid & 3;
    const int row0 = blockIdx.x * 128;
    const int col0 = blockIdx.y * 128;
    const int lrow = lane & 15, lcol = (lane >> 4) << 3;

    auto sAh = [&](int s) { return (__nv_bfloat16*)(smem + s * G1_STAGE); };
    auto sAl = [&](int s) { return (__nv_bfloat16*)(smem + s * G1_STAGE + 18432); };
    auto sBh = [&](int s) { return (__nv_bfloat16*)(smem + s * G1_STAGE + 36864); };
    auto sBl = [&](int s) { return (__nv_bfloat16*)(smem + s * G1_STAGE + 49920); };

    auto issue = [&](int k0_idx, int s) {
        const int k0 = k0_idx * 48;
        __nv_bfloat16 *ah = sAh(s), *al = sAl(s), *bh = sBh(s), *bl = sBl(s);
        for (int idx = tid; idx < 128 * 6; idx += 256) {
            int r = idx / 6, cb = (idx % 6) * 8;
            size_t go = (size_t)(row0 + r) * WIN + k0 + cb;
            cp16(&ah[r * G1_AST + cb], &g_a_hi[go]);
            cp16(&al[r * G1_AST + cb], &g_a_lo[go]);
        }
        for (int idx = tid; idx < 48 * 16; idx += 256) {
            int r = idx / 16, cb = (idx % 16) * 8;
            int gn = col0 + cb;
            bool ok = gn < WIN;
            size_t go = ok ? (size_t)(k0 + r) * WIN + gn : 0;
            cp16_pred(&bh[r * G1_BST + cb], &g_w1h[go], ok);
            cp16_pred(&bl[r * G1_BST + cb], &g_w1l[go], ok);
        }
    };

    float acc1[4][4][4], acc2[4][4][4];
#pragma unroll
    for (int i = 0; i < 4; i++)
#pragma unroll
        for (int j = 0; j < 4; j++)
#pragma unroll
            for (int k = 0; k < 4; k++) { acc1[i][j][k] = 0.0f; acc2[i][j][k] = 0.0f; }

    issue(0, 0);
    cp_commit();

    for (int it = 0; it < 7; it++) {
        const int s = it & 1;
        if (it < 6) {
            issue(it + 1, s ^ 1);
            cp_commit();
            cp_wait<1>();
        } else {
            cp_wait<0>();
        }
        __syncthreads();

        __nv_bfloat16 *ah_s = sAh(s), *al_s = sAl(s), *bh_s = sBh(s), *bl_s = sBl(s);
#pragma unroll
        for (int ks = 0; ks < 3; ks++) {
            unsigned bh[2][4], bl[2][4];
#pragma unroll
            for (int nf2 = 0; nf2 < 2; nf2++) {
                ldsm_x4t(bh[nf2], sm_u32(&bh_s[(ks * 16 + lrow) * G1_BST + wn * 32 + nf2 * 16 + lcol]));
                ldsm_x4t(bl[nf2], sm_u32(&bl_s[(ks * 16 + lrow) * G1_BST + wn * 32 + nf2 * 16 + lcol]));
            }
            unsigned ah[4][4], al[4][4];
#pragma unroll
            for (int mf = 0; mf < 4; mf++) {
                ldsm_x4(ah[mf], sm_u32(&ah_s[(wm * 64 + mf * 16 + lrow) * G1_AST + ks * 16 + lcol]));
                ldsm_x4(al[mf], sm_u32(&al_s[(wm * 64 + mf * 16 + lrow) * G1_AST + ks * 16 + lcol]));
            }
#pragma unroll
            for (int mf = 0; mf < 4; mf++) {
#pragma unroll
                for (int nf2 = 0; nf2 < 2; nf2++) {
#pragma unroll
                    for (int h = 0; h < 2; h++) {
                        int n8 = nf2 * 2 + h;
                        mma16816(acc1[mf][n8], ah[mf], bh[nf2][2 * h], bh[nf2][2 * h + 1]);
                        mma16816(acc2[mf][n8], al[mf], bh[nf2][2 * h], bh[nf2][2 * h + 1]);
                        mma16816(acc2[mf][n8], ah[mf], bl[nf2][2 * h], bl[nf2][2 * h + 1]);
                    }
                }
            }
        }
        __syncthreads();
    }

    const int group = lane >> 2, tig = lane & 3;
#pragma unroll
    for (int mf = 0; mf < 4; mf++) {
#pragma unroll
        for (int n8 = 0; n8 < 4; n8++) {
            int gc = col0 + wn * 32 + n8 * 8 + 2 * tig;
            if (gc >= WIN) continue;
            float b0 = bias[gc], b1 = bias[gc + 1];
            int r0 = row0 + wm * 64 + mf * 16 + group;
#pragma unroll
            for (int half = 0; half < 2; half++) {
                int gr = r0 + half * 8;
                float t0 = tanhf(acc1[mf][n8][2 * half] + acc2[mf][n8][2 * half] + b0);
                float t1 = tanhf(acc1[mf][n8][2 * half + 1] + acc2[mf][n8][2 * half + 1] + b1);
                __nv_bfloat16 h0, l0, h1, l1;
                split_bf16(t0, h0, l0);
                split_bf16(t1, h1, l1);
                size_t go = (size_t)gr * WIN + gc;
                *reinterpret_cast<__nv_bfloat162*>(&g_h_hi[go]) = __nv_bfloat162{h0, h1};
                *reinterpret_cast<__nv_bfloat162*>(&g_h_lo[go]) = __nv_bfloat162{l0, l1};
            }
        }
    }
}

// ---------------- GEMM2: out = hidden@W2 + b2, dual-acc, 2 CTAs/SM ----------------
#define G2_BST 72
__global__ void __launch_bounds__(256, 2)
gemm2_kernel(const float* __restrict__ bias, float* __restrict__ out) {
    extern __shared__ char smem[];
    const int tid = threadIdx.x;
    const int wid = tid >> 5, lane = tid & 31;
    const int row0 = blockIdx.x * 128;
    const int lrow = lane & 15, lcol = (lane >> 4) << 3;

    auto sAh = [&](int s) { return (__nv_bfloat16*)(smem + s * G2_STAGE); };
    auto sAl = [&](int s) { return (__nv_bfloat16*)(smem + s * G2_STAGE + 18432); };
    auto sBh = [&](int s) { return (__nv_bfloat16*)(smem + s * G2_STAGE + 36864); };
    auto sBl = [&](int s) { return (__nv_bfloat16*)(smem + s * G2_STAGE + 43776); };

    auto issue = [&](int k0_idx, int s) {
        const int k0 = k0_idx * 48;
        __nv_bfloat16 *ah = sAh(s), *al = sAl(s), *bh = sBh(s), *bl = sBl(s);
        for (int idx = tid; idx < 128 * 6; idx += 256) {
            int r = idx / 6, cb = (idx % 6) * 8;
            size_t go = (size_t)(row0 + r) * WIN + k0 + cb;
            cp16(&ah[r * G1_AST + cb], &g_h_hi[go]);
            cp16(&al[r * G1_AST + cb], &g_h_lo[go]);
        }
        for (int idx = tid; idx < 48 * 6; idx += 256) {
            int r = idx / 6, cb = (idx % 6) * 8;
            size_t go = (size_t)(k0 + r) * OUTSZ + cb;
            cp16(&bh[r * G2_BST + cb], &g_w2h[go]);
            cp16(&bl[r * G2_BST + cb], &g_w2l[go]);
        }
    };

    float acc1[6][4], acc2[6][4];
#pragma unroll
    for (int i = 0; i < 6; i++)
#pragma unroll
        for (int k = 0; k < 4; k++) { acc1[i][k] = 0.0f; acc2[i][k] = 0.0f; }

    issue(0, 0);
    cp_commit();

    for (int it = 0; it < 7; it++) {
        const int s = it & 1;
        if (it < 6) {
            issue(it + 1, s ^ 1);
            cp_commit();
            cp_wait<1>();
        } else {
            cp_wait<0>();
        }
        __syncthreads();

        __nv_bfloat16 *ah_s = sAh(s), *al_s = sAl(s), *bh_s = sBh(s), *bl_s = sBl(s);
#pragma unroll
        for (int ks = 0; ks < 3; ks++) {
            unsigned ah[4], al[4];
            ldsm_x4(ah, sm_u32(&ah_s[(wid * 16 + lrow) * G1_AST + ks * 16 + lcol]));
            ldsm_x4(al, sm_u32(&al_s[(wid * 16 + lrow) * G1_AST + ks * 16 + lcol]));
#pragma unroll
            for (int nf2 = 0; nf2 < 3; nf2++) {
                unsigned bh[4], bl[4];
                ldsm_x4t(bh, sm_u32(&bh_s[(ks * 16 + lrow) * G2_BST + nf2 * 16 + lcol]));
                ldsm_x4t(bl, sm_u32(&bl_s[(ks * 16 + lrow) * G2_BST + nf2 * 16 + lcol]));
#pragma unroll
                for (int h = 0; h < 2; h++) {
                    int n8 = nf2 * 2 + h;
                    mma16816(acc1[n8], ah, bh[2 * h], bh[2 * h + 1]);
                    mma16816(acc2[n8], al, bh[2 * h], bh[2 * h + 1]);
                    mma16816(acc2[n8], ah, bl[2 * h], bl[2 * h + 1]);
                }
            }
        }
        __syncthreads();
    }

    const int group = lane >> 2, tig = lane & 3;
#pragma unroll
    for (int n8 = 0; n8 < 6; n8++) {
        int gc = n8 * 8 + 2 * tig;
        float b0 = bias[gc], b1 = bias[gc + 1];
        int r0 = row0 + wid * 16 + group;
#pragma unroll
        for (int half = 0; half < 2; half++) {
            int gr = r0 + half * 8;
            if (gr < N_ROWS) {
                float2 v = make_float2(acc1[n8][2 * half] + acc2[n8][2 * half] + b0,
                                       acc1[n8][2 * half + 1] + acc2[n8][2 * half + 1] + b1);
                *reinterpret_cast<float2*>(&out[(size_t)gr * OUTSZ + gc]) = v;
            }
        }
    }
}

// ---------------- launch ----------------
extern "C" void kernel_launch(void* const* d_in, const int* in_sizes, int n_in,
                              void* d_out, int out_size) {
    const float* x           = (const float*)d_in[0];
    const float* lvl_coef    = (const float*)d_in[1];
    const float* seas_coef   = (const float*)d_in[2];
    const float* seas_params = (const float*)d_in[3];
    const float* W_tanh      = (const float*)d_in[4];
    const float* b_tanh      = (const float*)d_in[5];
    const float* W_out       = (const float*)d_in[6];
    const float* b_out       = (const float*)d_in[7];
    float* out = (float*)d_out;

    cudaFuncSetAttribute(gemm1_kernel, cudaFuncAttributeMaxDynamicSharedMemorySize, G1_SMEM);
    cudaFuncSetAttribute(gemm2_kernel, cudaFuncAttributeMaxDynamicSharedMemorySize, G2_SMEM);

    wsplit1_kernel<<<(WIN * WIN + 255) / 256, 256>>>(W_tanh);
    wsplit2_kernel<<<(WIN * OUTSZ + 255) / 256, 256>>>(W_out);
    {
        unsigned total = (unsigned)(M_PAD - N_ROWS) * WIN;
        zero_tail_kernel<<<(total / 2 + 255) / 256, 256>>>();
    }
    // fused scan+gen at launch index 3 (profiled by the harness ncu capture)
    fused_scan_gen_kernel<<<148, 1024>>>(x, lvl_coef, seas_coef, seas_params, out);
    {
        dim3 grid(M_PAD / 128, 3);
        gemm1_kernel<<<grid, 256, G1_SMEM>>>(b_tanh);
    }
    loss_kernel<<<1, 1024>>>(out);
    {
        dim3 grid(M_PAD / 128);
        gemm2_kernel<<<grid, 256, G2_SMEM>>>(b_out, out);
    }
    (void)in_sizes; (void)n_in; (void)out_size;
}